// round 6
// baseline (speedup 1.0000x reference)
#include <cuda_runtime.h>
#include <math.h>
#include <stdint.h>

#define NN 100000
#define EE 600000
#define HH 128
#define LL 3
#define BB 16
#define NF 12
#define EF 3
#define BN_EPS 1e-5f
#define LN_EPS 1e-5f

// permuted tf32 weight scratch offsets
#define W1OFF 0                         // 3 x (128*256)
#define W2OFF (LL * 128 * 256)          // 3 x (256*128)
#define O1OFF (W2OFF + LL * 256 * 128)  // 512*128
#define O2OFF (O1OFF + 512 * 128)       // 128*128
#define WTOT  (O2OFF + 128 * 128)

// ---------------- scratch (static device globals; no runtime alloc) ----------
__device__ __align__(128) float g_hcat[(size_t)NN * 4 * HH];
__device__ __align__(128) float g_agg [(size_t)NN * HH];
__device__ __align__(128) float g_z1  [(size_t)NN * 2 * HH];
__device__ __align__(128) float g_wtf [WTOT];
__device__ float g_gsum[BB * HH];
__device__ float g_cnt [BB];
__device__ int   g_deg [NN];
__device__ int   g_rows[NN];
__device__ int   g_fill[NN];
__device__ __align__(128) float4 g_epack[EE];
__device__ int   g_bsum[128];
__device__ int   g_boff[128];

// ---------------- helpers ----------------------------------------------------
__device__ __forceinline__ uint32_t f2tf(float f) {
    uint32_t r;
    asm("cvt.rna.tf32.f32 %0, %1;" : "=r"(r) : "f"(f));
    return r;
}
__device__ __forceinline__ void mma_tf32(float* c, const uint32_t* a, const uint32_t* b) {
    asm volatile(
        "mma.sync.aligned.m16n8k8.row.col.f32.tf32.tf32.f32 "
        "{%0,%1,%2,%3},{%4,%5,%6,%7},{%8,%9},{%0,%1,%2,%3};\n"
        : "+f"(c[0]), "+f"(c[1]), "+f"(c[2]), "+f"(c[3])
        : "r"(a[0]), "r"(a[1]), "r"(a[2]), "r"(a[3]), "r"(b[0]), "r"(b[1]));
}
__device__ __forceinline__ uint32_t sptr(const void* p) {
    return (uint32_t)__cvta_generic_to_shared(p);
}
__device__ __forceinline__ void cp16(uint32_t d, const void* s, int sz) {
    asm volatile("cp.async.cg.shared.global [%0], [%1], 16, %2;\n"
                 :: "r"(d), "l"(s), "r"(sz));
}
__device__ __forceinline__ void cp_commit() {
    asm volatile("cp.async.commit_group;\n" ::: "memory");
}
template <int N> __device__ __forceinline__ void cp_wait() {
    asm volatile("cp.async.wait_group %0;\n" :: "n"(N) : "memory");
}

// ---------------- init / weight permute+convert -------------------------------
__global__ void k_init() {
    int i = blockIdx.x * blockDim.x + threadIdx.x;
    if (i < BB * HH) g_gsum[i] = 0.f;
    if (i < BB) g_cnt[i] = 0.f;
    if (i < NN) { g_deg[i] = 0; g_fill[i] = 0; }
}

// Permute [K,N] row-major weights into fragment-major tf32 layout:
// i = (((s*NWG + nw)*32 + lane)*4 + g)*4 + e
//   k = 8s + (lane&3) + 4*(e&1), n = nw*64 + (2g + (e>>1))*8 + (lane>>2)
__global__ void k_wt(const float* __restrict__ src, float* __restrict__ dst,
                     int K, int N) {
    int i = blockIdx.x * blockDim.x + threadIdx.x;
    if (i >= K * N) return;
    int e = i & 3, g = (i >> 2) & 3, lane = (i >> 4) & 31;
    int r = i >> 9;
    int NWG = N >> 6;
    int nw = r % NWG, s = r / NWG;
    int lc = lane & 3, lr = lane >> 2;
    int k = 8 * s + lc + 4 * (e & 1);
    int n = nw * 64 + (2 * g + (e >> 1)) * 8 + lr;
    dst[i] = __uint_as_float(f2tf(src[(size_t)k * N + n]));
}

__global__ void k_input(const float* __restrict__ x, const float* __restrict__ W,
                        const float* __restrict__ b) {
    int idx = blockIdx.x * blockDim.x + threadIdx.x;
    if (idx >= NN * HH) return;
    int n = idx >> 7, j = idx & 127;
    const float* xr = x + (size_t)n * NF;
    float acc = b[j];
#pragma unroll
    for (int f = 0; f < NF; f++) acc += xr[f] * W[f * HH + j];
    g_hcat[(size_t)n * 512 + j] = acc;
}

// ---------------- CSR build ----------------------------------------------------
__global__ void k_count(const int* __restrict__ ei) {
    int e = blockIdx.x * blockDim.x + threadIdx.x;
    if (e < EE) atomicAdd(&g_deg[ei[EE + e]], 1);
}
__global__ void k_scan1() {
    __shared__ int ss[256];
    int t = threadIdx.x;
    int base = blockIdx.x * 1024;
    int v[4], s = 0;
#pragma unroll
    for (int j = 0; j < 4; j++) {
        int i = base + t * 4 + j;
        v[j] = (i < NN) ? g_deg[i] : 0;
        s += v[j];
    }
    ss[t] = s;
    __syncthreads();
#pragma unroll
    for (int off = 1; off < 256; off <<= 1) {
        int a = (t >= off) ? ss[t - off] : 0;
        __syncthreads();
        ss[t] += a;
        __syncthreads();
    }
    if (t == 255) g_bsum[blockIdx.x] = ss[255];
    int run = ss[t] - s;
#pragma unroll
    for (int j = 0; j < 4; j++) {
        int i = base + t * 4 + j;
        if (i < NN) g_rows[i] = run;
        run += v[j];
    }
}
__global__ void k_scan2(int nb) {
    __shared__ int ss[128];
    int t = threadIdx.x;
    int v = (t < nb) ? g_bsum[t] : 0;
    ss[t] = v;
    __syncthreads();
#pragma unroll
    for (int off = 1; off < 128; off <<= 1) {
        int a = (t >= off) ? ss[t - off] : 0;
        __syncthreads();
        ss[t] += a;
        __syncthreads();
    }
    if (t < nb) g_boff[t] = ss[t] - v;
}
__global__ void k_scan3() {
    int i = blockIdx.x * blockDim.x + threadIdx.x;
    if (i < NN) g_rows[i] += g_boff[i >> 10];
}
__global__ void k_place(const int* __restrict__ ei, const float* __restrict__ ea) {
    int e = blockIdx.x * blockDim.x + threadIdx.x;
    if (e >= EE) return;
    int d = ei[EE + e];
    int p = g_rows[d] + atomicAdd(&g_fill[d], 1);
    float4 r;
    r.x = __int_as_float(ei[e]);
    r.y = ea[e * 3 + 0];
    r.z = ea[e * 3 + 1];
    r.w = ea[e * 3 + 2];
    g_epack[p] = r;
}

// ---------------- per-node gather aggregation (no atomics) --------------------
__global__ void k_gather(const float* __restrict__ eW, const float* __restrict__ eb,
                         const float* __restrict__ eps, int layer) {
    int warp = (blockIdx.x * blockDim.x + threadIdx.x) >> 5;
    int lane = threadIdx.x & 31;
    if (warp >= NN) return;
    int j = lane * 4;
    const float* W = eW + layer * EF * HH;
    float4 w0 = *(const float4*)(W + 0 * HH + j);
    float4 w1 = *(const float4*)(W + 1 * HH + j);
    float4 w2 = *(const float4*)(W + 2 * HH + j);
    float4 bv = *(const float4*)(eb + layer * HH + j);
    const float* hl = g_hcat + (size_t)layer * HH;
    float4 hd = *(const float4*)(hl + (size_t)warp * 512 + j);
    int start = g_rows[warp], deg = g_deg[warp];
    const float4* ep = g_epack + start;

    float e1 = 1.f + eps[layer];
    float dg = (float)deg;
    float ax = e1 * hd.x + dg * bv.x;
    float ay = e1 * hd.y + dg * bv.y;
    float az = e1 * hd.z + dg * bv.z;
    float aw = e1 * hd.w + dg * bv.w;
    float bx = 0.f, by = 0.f, bz = 0.f, bw = 0.f;

    int k = 0;
    for (; k + 2 <= deg; k += 2) {
        float4 r0 = ep[k], r1 = ep[k + 1];
        int s0 = __float_as_int(r0.x), s1 = __float_as_int(r1.x);
        float4 h0 = *(const float4*)(hl + (size_t)s0 * 512 + j);
        float4 h1 = *(const float4*)(hl + (size_t)s1 * 512 + j);
        ax += h0.x + r0.y * w0.x + r0.z * w1.x + r0.w * w2.x;
        ay += h0.y + r0.y * w0.y + r0.z * w1.y + r0.w * w2.y;
        az += h0.z + r0.y * w0.z + r0.z * w1.z + r0.w * w2.z;
        aw += h0.w + r0.y * w0.w + r0.z * w1.w + r0.w * w2.w;
        bx += h1.x + r1.y * w0.x + r1.z * w1.x + r1.w * w2.x;
        by += h1.y + r1.y * w0.y + r1.z * w1.y + r1.w * w2.y;
        bz += h1.z + r1.y * w0.z + r1.z * w1.z + r1.w * w2.z;
        bw += h1.w + r1.y * w0.w + r1.z * w1.w + r1.w * w2.w;
    }
    if (k < deg) {
        float4 r0 = ep[k];
        int s0 = __float_as_int(r0.x);
        float4 h0 = *(const float4*)(hl + (size_t)s0 * 512 + j);
        ax += h0.x + r0.y * w0.x + r0.z * w1.x + r0.w * w2.x;
        ay += h0.y + r0.y * w0.y + r0.z * w1.y + r0.w * w2.y;
        az += h0.z + r0.y * w0.z + r0.z * w1.z + r0.w * w2.z;
        aw += h0.w + r0.y * w0.w + r0.z * w1.w + r0.w * w2.w;
    }
    float4 o;
    o.x = __uint_as_float(f2tf(ax + bx));
    o.y = __uint_as_float(f2tf(ay + by));
    o.z = __uint_as_float(f2tf(az + bz));
    o.w = __uint_as_float(f2tf(aw + bw));
    *(float4*)(g_agg + (size_t)warp * HH + j) = o;
}

// ---------------- tf32 mma GEMM: 3-stage cp.async ring, 1 sync/chunk ----------
// EPI 0: bn+relu -> tf32                      (mlp1 -> z1)
// EPI 1: bn+relu + hres, fused LN -> fp32     (mlp2 -> hcat, OS=512)
// EPI 2: relu -> tf32                         (out1 -> z1)
// EPI 3: none -> fp32                         (out2 -> node_emb)
// Weights Wp are fragment-major permuted (see k_wt). A row-major (CVTA: fp32).
template <int K, int NC, int EPI, int CVTA>
__global__ void __launch_bounds__(256, 2)
k_gemm(const float* __restrict__ A, const float* __restrict__ Wp,
       const float* __restrict__ bias,
       const float* __restrict__ bng, const float* __restrict__ bnb,
       const float* __restrict__ bnrm, const float* __restrict__ bnrv,
       const float* __restrict__ hres,
       const float* __restrict__ lng, const float* __restrict__ lnb,
       float* __restrict__ out) {
    constexpr int NWG = NC / 64;       // warp cols (2 or 4)
    constexpr int MW_ = 8 / NWG;       // warp rows (4 or 2)
    constexpr int BM = MW_ * 32;       // 128 or 64
    constexpr int KC = 16;
    constexpr int CH = K / KC;
    constexpr int ABYTES = BM * 80;                 // stride 20 floats/row
    constexpr int BBYTES = 2 * NWG * 32 * 80;       // 80B per (ks,nw,lane)
    constexpr int STG = ABYTES + BBYTES;
    constexpr int OS = (EPI == 1) ? 512 : NC;

    extern __shared__ char dsm[];
    __shared__ float red[BM * 4];
    uint32_t sb = sptr(dsm);

    int t = threadIdx.x;
    int lane = t & 31, wid = t >> 5;
    int mw = (NC == 128) ? (wid >> 1) : (wid >> 2);
    int nw = (NC == 128) ? (wid & 1) : (wid & 3);
    int wrow = mw * 32, wcol = nw * 64;
    int lr = lane >> 2, lc = lane & 3;
    int n0 = blockIdx.x * BM;

    float acc[2][8][4];
#pragma unroll
    for (int mt = 0; mt < 2; mt++)
#pragma unroll
        for (int nt = 0; nt < 8; nt++)
#pragma unroll
            for (int i = 0; i < 4; i++) acc[mt][nt][i] = 0.f;

    auto load_tiles = [&](int c, int st) {
        uint32_t ab = sb + st * STG;
        uint32_t bb = ab + ABYTES;
#pragma unroll
        for (int i = 0; i < (BM * 4) / 256; i++) {
            int f = t + i * 256;
            int r = f >> 2, c4 = f & 3;
            int n = n0 + r;
            const float* src = A + (size_t)(n < NN ? n : 0) * K + c * KC + c4 * 4;
            cp16(ab + r * 80 + c4 * 16, src, n < NN ? 16 : 0);
        }
#pragma unroll
        for (int i = 0; i < (2 * NWG * 128) / 256; i++) {
            int f = t + i * 256;
            cp16(bb + (f >> 2) * 80 + (f & 3) * 16,
                 Wp + (size_t)c * KC * NC + f * 4, 16);
        }
    };

    load_tiles(0, 0);
    cp_commit();
    load_tiles(1, 1);
    cp_commit();
    for (int c = 0; c < CH; c++) {
        int st = c % 3;
        if (c + 1 < CH) cp_wait<1>(); else cp_wait<0>();
        __syncthreads();
        if (c + 2 < CH) {
            load_tiles(c + 2, (c + 2) % 3);
            cp_commit();
        }
        const float* As = (const float*)(dsm + st * STG);
        const char*  Bb = dsm + st * STG + ABYTES;
#pragma unroll
        for (int ks = 0; ks < 2; ks++) {
            int kk = ks * 8;
            uint32_t a[2][4];
#pragma unroll
            for (int mt = 0; mt < 2; mt++) {
                int base = (wrow + mt * 16 + lr) * 20 + kk + lc;
                if (CVTA) {
                    a[mt][0] = f2tf(As[base]);
                    a[mt][1] = f2tf(As[base + 160]);
                    a[mt][2] = f2tf(As[base + 4]);
                    a[mt][3] = f2tf(As[base + 164]);
                } else {
                    a[mt][0] = __float_as_uint(As[base]);
                    a[mt][1] = __float_as_uint(As[base + 160]);
                    a[mt][2] = __float_as_uint(As[base + 4]);
                    a[mt][3] = __float_as_uint(As[base + 164]);
                }
            }
            const float4* bf =
                (const float4*)(Bb + ((size_t)((ks * NWG + nw) * 32 + lane)) * 80);
            uint32_t b[8][2];
#pragma unroll
            for (int g = 0; g < 4; g++) {
                float4 f4 = bf[g];
                b[2 * g + 0][0] = __float_as_uint(f4.x);
                b[2 * g + 0][1] = __float_as_uint(f4.y);
                b[2 * g + 1][0] = __float_as_uint(f4.z);
                b[2 * g + 1][1] = __float_as_uint(f4.w);
            }
#pragma unroll
            for (int mt = 0; mt < 2; mt++)
#pragma unroll
                for (int nt = 0; nt < 8; nt++)
                    mma_tf32(acc[mt][nt], a[mt], b[nt]);
        }
    }

    // epilogue params per (nt, q) column
    float bsv[8][2], sc[8][2], sh[8][2];
#pragma unroll
    for (int nt = 0; nt < 8; nt++)
#pragma unroll
        for (int q = 0; q < 2; q++) {
            int col = wcol + nt * 8 + lc * 2 + q;
            bsv[nt][q] = bias[col];
            if (EPI == 0 || EPI == 1) {
                float s = bng[col] * rsqrtf(bnrv[col] + BN_EPS);
                sc[nt][q] = s;
                sh[nt][q] = bnb[col] - bnrm[col] * s;
            }
        }

    if (EPI == 1) {
#pragma unroll
        for (int mt = 0; mt < 2; mt++)
#pragma unroll
            for (int half = 0; half < 2; half++) {
                int row = wrow + mt * 16 + lr + half * 8;
                int n = n0 + row;
                float s = 0.f, sq = 0.f;
#pragma unroll
                for (int nt = 0; nt < 8; nt++)
#pragma unroll
                    for (int q = 0; q < 2; q++) {
                        int col = wcol + nt * 8 + lc * 2 + q;
                        float v = acc[mt][nt][half * 2 + q] + bsv[nt][q];
                        v = fmaxf(v * sc[nt][q] + sh[nt][q], 0.f);
                        if (n < NN) v += hres[(size_t)n * 512 + col];
                        acc[mt][nt][half * 2 + q] = v;
                        s += v;
                        sq += v * v;
                    }
                s  += __shfl_xor_sync(0xffffffffu, s, 1);
                sq += __shfl_xor_sync(0xffffffffu, sq, 1);
                s  += __shfl_xor_sync(0xffffffffu, s, 2);
                sq += __shfl_xor_sync(0xffffffffu, sq, 2);
                if (lc == 0) {
                    red[(row * 2 + nw) * 2 + 0] = s;
                    red[(row * 2 + nw) * 2 + 1] = sq;
                }
            }
        __syncthreads();
#pragma unroll
        for (int mt = 0; mt < 2; mt++)
#pragma unroll
            for (int half = 0; half < 2; half++) {
                int row = wrow + mt * 16 + lr + half * 8;
                int n = n0 + row;
                if (n >= NN) continue;
                float s  = red[(row * 2 + 0) * 2 + 0] + red[(row * 2 + 1) * 2 + 0];
                float sq = red[(row * 2 + 0) * 2 + 1] + red[(row * 2 + 1) * 2 + 1];
                float mu = s * (1.f / 128.f);
                float var = sq * (1.f / 128.f) - mu * mu;
                float inv = rsqrtf(var + LN_EPS);
#pragma unroll
                for (int nt = 0; nt < 8; nt++)
#pragma unroll
                    for (int q = 0; q < 2; q++) {
                        int col = wcol + nt * 8 + lc * 2 + q;
                        float v = acc[mt][nt][half * 2 + q];
                        out[(size_t)n * OS + col] =
                            (v - mu) * inv * lng[col] + lnb[col];
                    }
            }
        return;
    }

#pragma unroll
    for (int mt = 0; mt < 2; mt++)
#pragma unroll
        for (int half = 0; half < 2; half++) {
            int row = wrow + mt * 16 + lr + half * 8;
            int n = n0 + row;
            if (n >= NN) continue;
#pragma unroll
            for (int nt = 0; nt < 8; nt++)
#pragma unroll
                for (int q = 0; q < 2; q++) {
                    int col = wcol + nt * 8 + lc * 2 + q;
                    float v = acc[mt][nt][half * 2 + q] + bsv[nt][q];
                    if (EPI == 0) v = fmaxf(v * sc[nt][q] + sh[nt][q], 0.f);
                    if (EPI == 2) v = fmaxf(v, 0.f);
                    if (EPI == 0 || EPI == 2) v = __uint_as_float(f2tf(v));
                    out[(size_t)n * OS + col] = v;
                }
        }
}

// ---------------- pool ---------------------------------------------------------
__global__ void k_pool(const int* __restrict__ batch, const float* __restrict__ emb) {
    int c = blockIdx.x;
    int j = threadIdx.x;
    int n0 = c * 32;
    __shared__ int sb[32];
    if (j < 32) sb[j] = (n0 + j < NN) ? batch[n0 + j] : -1;
    __syncthreads();
    float acc = 0.f;
    int bcur = sb[0];
    for (int m = 0; m < 32; m++) {
        int b = sb[m];
        if (b < 0) break;
        if (b != bcur) {
            atomicAdd(&g_gsum[bcur * HH + j], acc);
            acc = 0.f;
            bcur = b;
        }
        acc += emb[(size_t)(n0 + m) * HH + j];
    }
    if (bcur >= 0) atomicAdd(&g_gsum[bcur * HH + j], acc);
    if (j == 0) {
        float cn = 0.f;
        int bc = sb[0];
        for (int m = 0; m < 32; m++) {
            int b = sb[m];
            if (b < 0) break;
            if (b != bc) { atomicAdd(&g_cnt[bc], cn); cn = 0.f; bc = b; }
            cn += 1.f;
        }
        if (bc >= 0) atomicAdd(&g_cnt[bc], cn);
    }
}

__global__ void k_finish(float* __restrict__ out_graph) {
    int i = blockIdx.x * blockDim.x + threadIdx.x;
    if (i >= BB * HH) return;
    out_graph[i] = g_gsum[i] / fmaxf(g_cnt[i >> 7], 1.f);
}

// ---------------- launcher ------------------------------------------------------
extern "C" void kernel_launch(void* const* d_in, const int* in_sizes, int n_in,
                              void* d_out, int out_size) {
    const float* x      = (const float*)d_in[0];
    const int*   ei     = (const int*)  d_in[1];
    const float* ea     = (const float*)d_in[2];
    const int*   batch  = (const int*)  d_in[3];
    const float* in_W   = (const float*)d_in[4];
    const float* in_b   = (const float*)d_in[5];
    const float* edge_W = (const float*)d_in[6];
    const float* edge_b = (const float*)d_in[7];
    const float* mlp_W1 = (const float*)d_in[8];
    const float* mlp_b1 = (const float*)d_in[9];
    const float* bn1_g  = (const float*)d_in[10];
    const float* bn1_b  = (const float*)d_in[11];
    const float* bn1_rm = (const float*)d_in[12];
    const float* bn1_rv = (const float*)d_in[13];
    const float* mlp_W2 = (const float*)d_in[14];
    const float* mlp_b2 = (const float*)d_in[15];
    const float* bn2_g  = (const float*)d_in[16];
    const float* bn2_b  = (const float*)d_in[17];
    const float* bn2_rm = (const float*)d_in[18];
    const float* bn2_rv = (const float*)d_in[19];
    const float* eps    = (const float*)d_in[20];
    const float* ln_g   = (const float*)d_in[21];
    const float* ln_b   = (const float*)d_in[22];
    const float* out_W1 = (const float*)d_in[23];
    const float* out_b1 = (const float*)d_in[24];
    const float* out_W2 = (const float*)d_in[25];
    const float* out_b2 = (const float*)d_in[26];

    float* node_emb  = (float*)d_out;
    float* graph_emb = (float*)d_out + (size_t)NN * HH;

    float* g_hcat_p; cudaGetSymbolAddress((void**)&g_hcat_p, g_hcat);
    float* g_agg_p;  cudaGetSymbolAddress((void**)&g_agg_p,  g_agg);
    float* g_z1_p;   cudaGetSymbolAddress((void**)&g_z1_p,   g_z1);
    float* g_wtf_p;  cudaGetSymbolAddress((void**)&g_wtf_p,  g_wtf);

    // dynamic smem: 3 stages of (A + B) tiles
    const int SM256 = 3 * (64 * 80 + 2 * 4 * 32 * 80);   // 76800
    const int SM128 = 3 * (128 * 80 + 2 * 2 * 32 * 80);  // 61440
    cudaFuncSetAttribute(k_gemm<128, 256, 0, 0>,
                         cudaFuncAttributeMaxDynamicSharedMemorySize, SM256);
    cudaFuncSetAttribute(k_gemm<256, 128, 1, 0>,
                         cudaFuncAttributeMaxDynamicSharedMemorySize, SM128);
    cudaFuncSetAttribute(k_gemm<512, 128, 2, 1>,
                         cudaFuncAttributeMaxDynamicSharedMemorySize, SM128);
    cudaFuncSetAttribute(k_gemm<128, 128, 3, 0>,
                         cudaFuncAttributeMaxDynamicSharedMemorySize, SM128);

    const int NT = 256;
    k_init<<<(NN + NT - 1) / NT, NT>>>();
    for (int l = 0; l < LL; l++) {
        k_wt<<<(128 * 256 + NT - 1) / NT, NT>>>(
            mlp_W1 + (size_t)l * 128 * 256, g_wtf_p + W1OFF + (size_t)l * 128 * 256,
            128, 256);
        k_wt<<<(256 * 128 + NT - 1) / NT, NT>>>(
            mlp_W2 + (size_t)l * 256 * 128, g_wtf_p + W2OFF + (size_t)l * 256 * 128,
            256, 128);
    }
    k_wt<<<(512 * 128 + NT - 1) / NT, NT>>>(out_W1, g_wtf_p + O1OFF, 512, 128);
    k_wt<<<(128 * 128 + NT - 1) / NT, NT>>>(out_W2, g_wtf_p + O2OFF, 128, 128);

    k_input<<<(NN * HH + NT - 1) / NT, NT>>>(x, in_W, in_b);

    // CSR build
    k_count<<<(EE + NT - 1) / NT, NT>>>(ei);
    k_scan1<<<(NN + 1023) / 1024, 256>>>();
    k_scan2<<<1, 128>>>((NN + 1023) / 1024);
    k_scan3<<<(NN + NT - 1) / NT, NT>>>();
    k_place<<<(EE + NT - 1) / NT, NT>>>(ei, ea);

    const int grid128 = (NN + 127) / 128;   // BM=128 (NC=128)
    const int grid64  = (NN + 63) / 64;     // BM=64  (NC=256)
    for (int l = 0; l < LL; l++) {
        k_gather<<<(NN * 32 + NT - 1) / NT, NT>>>(edge_W, edge_b, eps, l);
        k_gemm<128, 256, 0, 0><<<grid64, 256, SM256>>>(
            g_agg_p, g_wtf_p + W1OFF + (size_t)l * 128 * 256, mlp_b1 + l * 256,
            bn1_g + l * 256, bn1_b + l * 256, bn1_rm + l * 256, bn1_rv + l * 256,
            nullptr, nullptr, nullptr, g_z1_p);
        k_gemm<256, 128, 1, 0><<<grid128, 256, SM128>>>(
            g_z1_p, g_wtf_p + W2OFF + (size_t)l * 256 * 128, mlp_b2 + l * 128,
            bn2_g + l * 128, bn2_b + l * 128, bn2_rm + l * 128, bn2_rv + l * 128,
            g_hcat_p + l * HH, ln_g + l * 128, ln_b + l * 128,
            g_hcat_p + (l + 1) * HH);
    }
    k_gemm<512, 128, 2, 1><<<grid128, 256, SM128>>>(
        g_hcat_p, g_wtf_p + O1OFF, out_b1, nullptr, nullptr, nullptr, nullptr,
        nullptr, nullptr, nullptr, g_z1_p);
    k_gemm<128, 128, 3, 0><<<grid128, 256, SM128>>>(
        g_z1_p, g_wtf_p + O2OFF, out_b2, nullptr, nullptr, nullptr, nullptr,
        nullptr, nullptr, nullptr, node_emb);

    k_pool<<<(NN + 31) / 32, 128>>>(batch, node_emb);
    k_finish<<<(BB * HH + NT - 1) / NT, NT>>>(graph_emb);
}

// round 7
// speedup vs baseline: 1.0652x; 1.0652x over previous
#include <cuda_runtime.h>
#include <math.h>
#include <stdint.h>

#define NN 100000
#define EE 600000
#define HH 128
#define LL 3
#define BB 16
#define NF 12
#define EF 3
#define BN_EPS 1e-5f
#define LN_EPS 1e-5f

// permuted tf32 weight scratch offsets (floats)
#define W1OFF 0                         // 3 x (128*256)
#define W2OFF (LL * 128 * 256)          // 3 x (256*128)
#define O1OFF (W2OFF + LL * 256 * 128)  // 512*128
#define O2OFF (O1OFF + 512 * 128)       // 128*128
#define WTOT  (O2OFF + 128 * 128)

// ---------------- scratch (static device globals; no runtime alloc) ----------
__device__ __align__(128) float g_hcat[(size_t)NN * 4 * HH];
__device__ __align__(128) float g_agg [(size_t)NN * HH];
__device__ __align__(128) float g_z1  [(size_t)NN * 2 * HH];
__device__ __align__(128) float g_wtf [WTOT];
__device__ float g_gsum[BB * HH];
__device__ float g_cnt [BB];
__device__ int   g_deg [NN];
__device__ int   g_rows[NN];
__device__ int   g_fill[NN];
__device__ __align__(128) float4 g_epack[EE];
__device__ int   g_bsum[128];
__device__ int   g_boff[128];

// ---------------- helpers ----------------------------------------------------
__device__ __forceinline__ uint32_t f2tf(float f) {
    uint32_t r;
    asm("cvt.rna.tf32.f32 %0, %1;" : "=r"(r) : "f"(f));
    return r;
}
__device__ __forceinline__ void mma_tf32(float* c, const uint32_t* a, const uint32_t* b) {
    asm volatile(
        "mma.sync.aligned.m16n8k8.row.col.f32.tf32.tf32.f32 "
        "{%0,%1,%2,%3},{%4,%5,%6,%7},{%8,%9},{%0,%1,%2,%3};\n"
        : "+f"(c[0]), "+f"(c[1]), "+f"(c[2]), "+f"(c[3])
        : "r"(a[0]), "r"(a[1]), "r"(a[2]), "r"(a[3]), "r"(b[0]), "r"(b[1]));
}
__device__ __forceinline__ uint32_t sptr(const void* p) {
    return (uint32_t)__cvta_generic_to_shared(p);
}
__device__ __forceinline__ void cp16(uint32_t d, const void* s, int sz) {
    asm volatile("cp.async.cg.shared.global [%0], [%1], 16, %2;\n"
                 :: "r"(d), "l"(s), "r"(sz));
}
__device__ __forceinline__ void cp_commit() {
    asm volatile("cp.async.commit_group;\n" ::: "memory");
}
template <int N> __device__ __forceinline__ void cp_wait() {
    asm volatile("cp.async.wait_group %0;\n" :: "n"(N) : "memory");
}

// ---------------- prep: zero counters + permute/convert ALL weights ------------
// fragment-major layout: i = (((s*NWG + nw)*32 + lane)*4 + g)*4 + e
//   k = 8s + (lane&3) + 4*(e&1), n = nw*64 + (2g + (e>>1))*8 + (lane>>2)
__global__ void k_prep(const float* __restrict__ w1, const float* __restrict__ w2,
                       const float* __restrict__ o1, const float* __restrict__ o2) {
    int i = blockIdx.x * blockDim.x + threadIdx.x;
    if (i < BB * HH) g_gsum[i] = 0.f;
    if (i < BB) g_cnt[i] = 0.f;
    if (i < NN) { g_deg[i] = 0; g_fill[i] = 0; }
    if (i >= WTOT) return;
    const float* src;
    int K, N, rel;
    if (i < W2OFF) {
        int l = i >> 15; rel = i & 32767;
        src = w1 + (size_t)l * 32768; K = 128; N = 256;
    } else if (i < O1OFF) {
        int j = i - W2OFF;
        int l = j >> 15; rel = j & 32767;
        src = w2 + (size_t)l * 32768; K = 256; N = 128;
    } else if (i < O2OFF) {
        rel = i - O1OFF; src = o1; K = 512; N = 128;
    } else {
        rel = i - O2OFF; src = o2; K = 128; N = 128;
    }
    int e = rel & 3, g = (rel >> 2) & 3, lane = (rel >> 4) & 31;
    int r = rel >> 9;
    int NWG = N >> 6;
    int nw = r % NWG, s = r / NWG;
    int lc = lane & 3, lr = lane >> 2;
    int k = 8 * s + lc + 4 * (e & 1);
    int n = nw * 64 + (2 * g + (e >> 1)) * 8 + lr;
    g_wtf[i] = __uint_as_float(f2tf(src[(size_t)k * N + n]));
}

__global__ void k_input(const float* __restrict__ x, const float* __restrict__ W,
                        const float* __restrict__ b) {
    int idx = blockIdx.x * blockDim.x + threadIdx.x;
    if (idx >= NN * HH) return;
    int n = idx >> 7, j = idx & 127;
    const float* xr = x + (size_t)n * NF;
    float acc = b[j];
#pragma unroll
    for (int f = 0; f < NF; f++) acc += xr[f] * W[f * HH + j];
    g_hcat[(size_t)n * 512 + j] = acc;
}

// ---------------- CSR build ----------------------------------------------------
__global__ void k_count(const int* __restrict__ ei) {
    int e = blockIdx.x * blockDim.x + threadIdx.x;
    if (e < EE) atomicAdd(&g_deg[ei[EE + e]], 1);
}
__global__ void k_scan1() {
    __shared__ int ss[256];
    int t = threadIdx.x;
    int base = blockIdx.x * 1024;
    int v[4], s = 0;
#pragma unroll
    for (int j = 0; j < 4; j++) {
        int i = base + t * 4 + j;
        v[j] = (i < NN) ? g_deg[i] : 0;
        s += v[j];
    }
    ss[t] = s;
    __syncthreads();
#pragma unroll
    for (int off = 1; off < 256; off <<= 1) {
        int a = (t >= off) ? ss[t - off] : 0;
        __syncthreads();
        ss[t] += a;
        __syncthreads();
    }
    if (t == 255) g_bsum[blockIdx.x] = ss[255];
    int run = ss[t] - s;
#pragma unroll
    for (int j = 0; j < 4; j++) {
        int i = base + t * 4 + j;
        if (i < NN) g_rows[i] = run;
        run += v[j];
    }
}
__global__ void k_scan2(int nb) {
    __shared__ int ss[128];
    int t = threadIdx.x;
    int v = (t < nb) ? g_bsum[t] : 0;
    ss[t] = v;
    __syncthreads();
#pragma unroll
    for (int off = 1; off < 128; off <<= 1) {
        int a = (t >= off) ? ss[t - off] : 0;
        __syncthreads();
        ss[t] += a;
        __syncthreads();
    }
    if (t < nb) g_boff[t] = ss[t] - v;
}
// place packed edge record; block offset folded in (no scan3 kernel)
__global__ void k_place(const int* __restrict__ ei, const float* __restrict__ ea) {
    int e = blockIdx.x * blockDim.x + threadIdx.x;
    if (e >= EE) return;
    int d = ei[EE + e];
    int p = g_rows[d] + g_boff[d >> 10] + atomicAdd(&g_fill[d], 1);
    float4 r;
    r.x = __int_as_float(ei[e]);
    r.y = ea[e * 3 + 0];
    r.z = ea[e * 3 + 1];
    r.w = ea[e * 3 + 2];
    g_epack[p] = r;
}

// ---------------- per-node gather aggregation (no atomics, 4-way MLP) ---------
__global__ void k_gather(const float* __restrict__ eW, const float* __restrict__ eb,
                         const float* __restrict__ eps, int layer) {
    int warp = (blockIdx.x * blockDim.x + threadIdx.x) >> 5;
    int lane = threadIdx.x & 31;
    if (warp >= NN) return;
    int j = lane * 4;
    const float* W = eW + layer * EF * HH;
    float4 w0 = *(const float4*)(W + 0 * HH + j);
    float4 w1 = *(const float4*)(W + 1 * HH + j);
    float4 w2 = *(const float4*)(W + 2 * HH + j);
    float4 bv = *(const float4*)(eb + layer * HH + j);
    const float* hl = g_hcat + (size_t)layer * HH;
    float4 hd = *(const float4*)(hl + (size_t)warp * 512 + j);
    int start = g_rows[warp] + g_boff[warp >> 10];
    int deg = g_deg[warp];
    const float4* ep = g_epack + start;

    float e1 = 1.f + eps[layer];
    float dg = (float)deg;
    float ax = e1 * hd.x + dg * bv.x;
    float ay = e1 * hd.y + dg * bv.y;
    float az = e1 * hd.z + dg * bv.z;
    float aw = e1 * hd.w + dg * bv.w;
    float bx = 0.f, by = 0.f, bz = 0.f, bw = 0.f;

    int k = 0;
    for (; k + 4 <= deg; k += 4) {
        float4 r0 = ep[k], r1 = ep[k + 1], r2 = ep[k + 2], r3 = ep[k + 3];
        const float4* p0 = (const float4*)(hl + (size_t)__float_as_int(r0.x) * 512 + j);
        const float4* p1 = (const float4*)(hl + (size_t)__float_as_int(r1.x) * 512 + j);
        const float4* p2 = (const float4*)(hl + (size_t)__float_as_int(r2.x) * 512 + j);
        const float4* p3 = (const float4*)(hl + (size_t)__float_as_int(r3.x) * 512 + j);
        float4 h0 = *p0, h1 = *p1, h2 = *p2, h3 = *p3;
        ax += h0.x + r0.y * w0.x + r0.z * w1.x + r0.w * w2.x;
        ay += h0.y + r0.y * w0.y + r0.z * w1.y + r0.w * w2.y;
        az += h0.z + r0.y * w0.z + r0.z * w1.z + r0.w * w2.z;
        aw += h0.w + r0.y * w0.w + r0.z * w1.w + r0.w * w2.w;
        bx += h1.x + r1.y * w0.x + r1.z * w1.x + r1.w * w2.x;
        by += h1.y + r1.y * w0.y + r1.z * w1.y + r1.w * w2.y;
        bz += h1.z + r1.y * w0.z + r1.z * w1.z + r1.w * w2.z;
        bw += h1.w + r1.y * w0.w + r1.z * w1.w + r1.w * w2.w;
        ax += h2.x + r2.y * w0.x + r2.z * w1.x + r2.w * w2.x;
        ay += h2.y + r2.y * w0.y + r2.z * w1.y + r2.w * w2.y;
        az += h2.z + r2.y * w0.z + r2.z * w1.z + r2.w * w2.z;
        aw += h2.w + r2.y * w0.w + r2.z * w1.w + r2.w * w2.w;
        bx += h3.x + r3.y * w0.x + r3.z * w1.x + r3.w * w2.x;
        by += h3.y + r3.y * w0.y + r3.z * w1.y + r3.w * w2.y;
        bz += h3.z + r3.y * w0.z + r3.z * w1.z + r3.w * w2.z;
        bw += h3.w + r3.y * w0.w + r3.z * w1.w + r3.w * w2.w;
    }
    for (; k < deg; k++) {
        float4 r0 = ep[k];
        float4 h0 = *(const float4*)(hl + (size_t)__float_as_int(r0.x) * 512 + j);
        ax += h0.x + r0.y * w0.x + r0.z * w1.x + r0.w * w2.x;
        ay += h0.y + r0.y * w0.y + r0.z * w1.y + r0.w * w2.y;
        az += h0.z + r0.y * w0.z + r0.z * w1.z + r0.w * w2.z;
        aw += h0.w + r0.y * w0.w + r0.z * w1.w + r0.w * w2.w;
    }
    float4 o;
    o.x = __uint_as_float(f2tf(ax + bx));
    o.y = __uint_as_float(f2tf(ay + by));
    o.z = __uint_as_float(f2tf(az + bz));
    o.w = __uint_as_float(f2tf(aw + bw));
    *(float4*)(g_agg + (size_t)warp * HH + j) = o;
}

// ---------------- tf32 mma GEMM (mlp1 / mlp2), 3-stage cp.async ring ----------
// EPI 0: bn+relu -> tf32                      (mlp1 -> z1)
// EPI 1: bn+relu + hres, fused LN -> fp32     (mlp2 -> hcat, OS=512)
template <int K, int NC, int EPI>
__global__ void __launch_bounds__(256, 2)
k_gemm(const float* __restrict__ A, const float* __restrict__ Wp,
       const float* __restrict__ bias,
       const float* __restrict__ bng, const float* __restrict__ bnb,
       const float* __restrict__ bnrm, const float* __restrict__ bnrv,
       const float* __restrict__ hres,
       const float* __restrict__ lng, const float* __restrict__ lnb,
       float* __restrict__ out) {
    constexpr int NWG = NC / 64;
    constexpr int MW_ = 8 / NWG;
    constexpr int BM = MW_ * 32;
    constexpr int KC = 16;
    constexpr int CH = K / KC;
    constexpr int ABYTES = BM * 80;
    constexpr int BBYTES = 2 * NWG * 32 * 80;
    constexpr int STG = ABYTES + BBYTES;
    constexpr int OS = (EPI == 1) ? 512 : NC;

    extern __shared__ char dsm[];
    __shared__ float red[BM * 4];
    uint32_t sb = sptr(dsm);

    int t = threadIdx.x;
    int lane = t & 31, wid = t >> 5;
    int mw = (NC == 128) ? (wid >> 1) : (wid >> 2);
    int nw = (NC == 128) ? (wid & 1) : (wid & 3);
    int wrow = mw * 32, wcol = nw * 64;
    int lr = lane >> 2, lc = lane & 3;
    int n0 = blockIdx.x * BM;

    float acc[2][8][4];
#pragma unroll
    for (int mt = 0; mt < 2; mt++)
#pragma unroll
        for (int nt = 0; nt < 8; nt++)
#pragma unroll
            for (int i = 0; i < 4; i++) acc[mt][nt][i] = 0.f;

    auto load_tiles = [&](int c, int st) {
        uint32_t ab = sb + st * STG;
        uint32_t bb = ab + ABYTES;
#pragma unroll
        for (int i = 0; i < (BM * 4) / 256; i++) {
            int f = t + i * 256;
            int r = f >> 2, c4 = f & 3;
            int n = n0 + r;
            const float* src = A + (size_t)(n < NN ? n : 0) * K + c * KC + c4 * 4;
            cp16(ab + r * 80 + c4 * 16, src, n < NN ? 16 : 0);
        }
#pragma unroll
        for (int i = 0; i < (2 * NWG * 128) / 256; i++) {
            int f = t + i * 256;
            cp16(bb + (f >> 2) * 80 + (f & 3) * 16,
                 Wp + (size_t)c * KC * NC + f * 4, 16);
        }
    };

    load_tiles(0, 0);
    cp_commit();
    load_tiles(1, 1);
    cp_commit();
    for (int c = 0; c < CH; c++) {
        int st = c % 3;
        if (c + 1 < CH) cp_wait<1>(); else cp_wait<0>();
        __syncthreads();
        if (c + 2 < CH) {
            load_tiles(c + 2, (c + 2) % 3);
            cp_commit();
        }
        const float* As = (const float*)(dsm + st * STG);
        const char*  Bb = dsm + st * STG + ABYTES;
#pragma unroll
        for (int ks = 0; ks < 2; ks++) {
            int kk = ks * 8;
            uint32_t a[2][4];
#pragma unroll
            for (int mt = 0; mt < 2; mt++) {
                int base = (wrow + mt * 16 + lr) * 20 + kk + lc;
                a[mt][0] = __float_as_uint(As[base]);
                a[mt][1] = __float_as_uint(As[base + 160]);
                a[mt][2] = __float_as_uint(As[base + 4]);
                a[mt][3] = __float_as_uint(As[base + 164]);
            }
            const float4* bf =
                (const float4*)(Bb + ((size_t)((ks * NWG + nw) * 32 + lane)) * 80);
            uint32_t b[8][2];
#pragma unroll
            for (int g = 0; g < 4; g++) {
                float4 f4 = bf[g];
                b[2 * g + 0][0] = __float_as_uint(f4.x);
                b[2 * g + 0][1] = __float_as_uint(f4.y);
                b[2 * g + 1][0] = __float_as_uint(f4.z);
                b[2 * g + 1][1] = __float_as_uint(f4.w);
            }
#pragma unroll
            for (int mt = 0; mt < 2; mt++)
#pragma unroll
                for (int nt = 0; nt < 8; nt++)
                    mma_tf32(acc[mt][nt], a[mt], b[nt]);
        }
    }

    float bsv[8][2], sc[8][2], sh[8][2];
#pragma unroll
    for (int nt = 0; nt < 8; nt++)
#pragma unroll
        for (int q = 0; q < 2; q++) {
            int col = wcol + nt * 8 + lc * 2 + q;
            bsv[nt][q] = bias[col];
            float s = bng[col] * rsqrtf(bnrv[col] + BN_EPS);
            sc[nt][q] = s;
            sh[nt][q] = bnb[col] - bnrm[col] * s;
        }

    if (EPI == 1) {
#pragma unroll
        for (int mt = 0; mt < 2; mt++)
#pragma unroll
            for (int half = 0; half < 2; half++) {
                int row = wrow + mt * 16 + lr + half * 8;
                int n = n0 + row;
                float s = 0.f, sq = 0.f;
#pragma unroll
                for (int nt = 0; nt < 8; nt++)
#pragma unroll
                    for (int q = 0; q < 2; q++) {
                        int col = wcol + nt * 8 + lc * 2 + q;
                        float v = acc[mt][nt][half * 2 + q] + bsv[nt][q];
                        v = fmaxf(v * sc[nt][q] + sh[nt][q], 0.f);
                        if (n < NN) v += hres[(size_t)n * 512 + col];
                        acc[mt][nt][half * 2 + q] = v;
                        s += v;
                        sq += v * v;
                    }
                s  += __shfl_xor_sync(0xffffffffu, s, 1);
                sq += __shfl_xor_sync(0xffffffffu, sq, 1);
                s  += __shfl_xor_sync(0xffffffffu, s, 2);
                sq += __shfl_xor_sync(0xffffffffu, sq, 2);
                if (lc == 0) {
                    red[(row * 2 + nw) * 2 + 0] = s;
                    red[(row * 2 + nw) * 2 + 1] = sq;
                }
            }
        __syncthreads();
#pragma unroll
        for (int mt = 0; mt < 2; mt++)
#pragma unroll
            for (int half = 0; half < 2; half++) {
                int row = wrow + mt * 16 + lr + half * 8;
                int n = n0 + row;
                if (n >= NN) continue;
                float s  = red[(row * 2 + 0) * 2 + 0] + red[(row * 2 + 1) * 2 + 0];
                float sq = red[(row * 2 + 0) * 2 + 1] + red[(row * 2 + 1) * 2 + 1];
                float mu = s * (1.f / 128.f);
                float var = sq * (1.f / 128.f) - mu * mu;
                float inv = rsqrtf(var + LN_EPS);
#pragma unroll
                for (int nt = 0; nt < 8; nt++)
#pragma unroll
                    for (int q = 0; q < 2; q++) {
                        int col = wcol + nt * 8 + lc * 2 + q;
                        float v = acc[mt][nt][half * 2 + q];
                        out[(size_t)n * OS + col] =
                            (v - mu) * inv * lng[col] + lnb[col];
                    }
            }
        return;
    }

#pragma unroll
    for (int mt = 0; mt < 2; mt++)
#pragma unroll
        for (int half = 0; half < 2; half++) {
            int row = wrow + mt * 16 + lr + half * 8;
            int n = n0 + row;
            if (n >= NN) continue;
#pragma unroll
            for (int nt = 0; nt < 8; nt++)
#pragma unroll
                for (int q = 0; q < 2; q++) {
                    int col = wcol + nt * 8 + lc * 2 + q;
                    float v = acc[mt][nt][half * 2 + q] + bsv[nt][q];
                    v = fmaxf(v * sc[nt][q] + sh[nt][q], 0.f);
                    out[(size_t)n * OS + col] = __uint_as_float(f2tf(v));
                }
        }
}

// ---------------- fused output head: node_emb = relu(cat@W1+b1)@W2 + b2 -------
// NC=128, BM=128, NWG=2. First GEMM K=512 (A=hcat fp32, converted at frag load),
// z tile kept in smem (tf32 bits, stride 132), second GEMM K=128 over W2p.
__global__ void __launch_bounds__(256, 2)
k_gemm_out(const float* __restrict__ A, const float* __restrict__ W1p,
           const float* __restrict__ W2p,
           const float* __restrict__ b1, const float* __restrict__ b2,
           float* __restrict__ out) {
    constexpr int NWG = 2, BM = 128, KC = 16, K = 512, NC = 128;
    constexpr int CH = K / KC;                   // 32
    constexpr int ABYTES = BM * 80;              // 10240
    constexpr int BBYTES = 2 * NWG * 32 * 80;    // 10240
    constexpr int STG = ABYTES + BBYTES;         // 20480
    constexpr int ZOFF = 0;                      // z tile: 128 x 132 f32 = 67584B
    constexpr int B2OFF = 67584;                 // 3 x 10240 W2 chunk bufs

    extern __shared__ char dsm[];
    uint32_t sb = sptr(dsm);

    int t = threadIdx.x;
    int lane = t & 31, wid = t >> 5;
    int mw = wid >> 1, nw = wid & 1;
    int wrow = mw * 32, wcol = nw * 64;
    int lr = lane >> 2, lc = lane & 3;
    int n0 = blockIdx.x * BM;

    float acc[2][8][4];
#pragma unroll
    for (int mt = 0; mt < 2; mt++)
#pragma unroll
        for (int nt = 0; nt < 8; nt++)
#pragma unroll
            for (int i = 0; i < 4; i++) acc[mt][nt][i] = 0.f;

    auto load_tiles = [&](int c, int st) {
        uint32_t ab = sb + st * STG;
        uint32_t bb = ab + ABYTES;
#pragma unroll
        for (int i = 0; i < 2; i++) {
            int f = t + i * 256;
            int r = f >> 2, c4 = f & 3;
            int n = n0 + r;
            const float* src = A + (size_t)(n < NN ? n : 0) * K + c * KC + c4 * 4;
            cp16(ab + r * 80 + c4 * 16, src, n < NN ? 16 : 0);
        }
#pragma unroll
        for (int i = 0; i < 2; i++) {
            int f = t + i * 256;
            cp16(bb + (f >> 2) * 80 + (f & 3) * 16,
                 W1p + (size_t)c * KC * NC + f * 4, 16);
        }
    };
    auto load_w2 = [&](int c2, int jbuf) {
        uint32_t bb = sb + B2OFF + jbuf * BBYTES;
#pragma unroll
        for (int i = 0; i < 2; i++) {
            int f = t + i * 256;
            cp16(bb + (f >> 2) * 80 + (f & 3) * 16,
                 W2p + (size_t)c2 * KC * NC + f * 4, 16);
        }
    };

    // ---- first GEMM: cat @ W1 ----
    load_tiles(0, 0);
    cp_commit();
    load_tiles(1, 1);
    cp_commit();
    for (int c = 0; c < CH; c++) {
        int st = c % 3;
        if (c + 1 < CH) cp_wait<1>(); else cp_wait<0>();
        __syncthreads();
        if (c + 2 < CH) {
            load_tiles(c + 2, (c + 2) % 3);
            cp_commit();
        }
        const float* As = (const float*)(dsm + st * STG);
        const char*  Bb = dsm + st * STG + ABYTES;
#pragma unroll
        for (int ks = 0; ks < 2; ks++) {
            int kk = ks * 8;
            uint32_t a[2][4];
#pragma unroll
            for (int mt = 0; mt < 2; mt++) {
                int base = (wrow + mt * 16 + lr) * 20 + kk + lc;
                a[mt][0] = f2tf(As[base]);
                a[mt][1] = f2tf(As[base + 160]);
                a[mt][2] = f2tf(As[base + 4]);
                a[mt][3] = f2tf(As[base + 164]);
            }
            const float4* bf =
                (const float4*)(Bb + ((size_t)((ks * NWG + nw) * 32 + lane)) * 80);
            uint32_t b[8][2];
#pragma unroll
            for (int g = 0; g < 4; g++) {
                float4 f4 = bf[g];
                b[2 * g + 0][0] = __float_as_uint(f4.x);
                b[2 * g + 0][1] = __float_as_uint(f4.y);
                b[2 * g + 1][0] = __float_as_uint(f4.z);
                b[2 * g + 1][1] = __float_as_uint(f4.w);
            }
#pragma unroll
            for (int mt = 0; mt < 2; mt++)
#pragma unroll
                for (int nt = 0; nt < 8; nt++)
                    mma_tf32(acc[mt][nt], a[mt], b[nt]);
        }
    }
    __syncthreads();   // all warps done with ring buffers before smem reuse

    // prefetch first two W2 chunks while computing z
    load_w2(0, 0);
    cp_commit();
    load_w2(1, 1);
    cp_commit();

    // ---- epilogue 1: z = tf32(relu(acc + b1)) -> smem (stride 132 floats) ----
    float* Zs = (float*)(dsm + ZOFF);
    {
        float bsv[8][2];
#pragma unroll
        for (int nt = 0; nt < 8; nt++)
#pragma unroll
            for (int q = 0; q < 2; q++)
                bsv[nt][q] = b1[wcol + nt * 8 + lc * 2 + q];
#pragma unroll
        for (int mt = 0; mt < 2; mt++)
#pragma unroll
            for (int half = 0; half < 2; half++) {
                int row = wrow + mt * 16 + lr + half * 8;
#pragma unroll
                for (int nt = 0; nt < 8; nt++)
#pragma unroll
                    for (int q = 0; q < 2; q++) {
                        int col = wcol + nt * 8 + lc * 2 + q;
                        float v = fmaxf(acc[mt][nt][half * 2 + q] + bsv[nt][q], 0.f);
                        Zs[row * 132 + col] = __uint_as_float(f2tf(v));
                    }
            }
    }
    __syncthreads();

    // ---- second GEMM: z @ W2 (K=128, 8 chunks) ----
#pragma unroll
    for (int mt = 0; mt < 2; mt++)
#pragma unroll
        for (int nt = 0; nt < 8; nt++)
#pragma unroll
            for (int i = 0; i < 4; i++) acc[mt][nt][i] = 0.f;

    for (int c2 = 0; c2 < 8; c2++) {
        int jb = c2 % 3;
        if (c2 + 1 < 8) cp_wait<1>(); else cp_wait<0>();
        __syncthreads();
        if (c2 + 2 < 8) {
            load_w2(c2 + 2, (c2 + 2) % 3);
            cp_commit();
        }
        const char* Bb = dsm + B2OFF + jb * BBYTES;
#pragma unroll
        for (int ks = 0; ks < 2; ks++) {
            int kk = ks * 8;
            uint32_t a[2][4];
#pragma unroll
            for (int mt = 0; mt < 2; mt++) {
                int base = (wrow + mt * 16 + lr) * 132 + c2 * KC + kk + lc;
                a[mt][0] = __float_as_uint(Zs[base]);
                a[mt][1] = __float_as_uint(Zs[base + 8 * 132]);
                a[mt][2] = __float_as_uint(Zs[base + 4]);
                a[mt][3] = __float_as_uint(Zs[base + 8 * 132 + 4]);
            }
            const float4* bf =
                (const float4*)(Bb + ((size_t)((ks * NWG + nw) * 32 + lane)) * 80);
            uint32_t b[8][2];
#pragma unroll
            for (int g = 0; g < 4; g++) {
                float4 f4 = bf[g];
                b[2 * g + 0][0] = __float_as_uint(f4.x);
                b[2 * g + 0][1] = __float_as_uint(f4.y);
                b[2 * g + 1][0] = __float_as_uint(f4.z);
                b[2 * g + 1][1] = __float_as_uint(f4.w);
            }
#pragma unroll
            for (int mt = 0; mt < 2; mt++)
#pragma unroll
                for (int nt = 0; nt < 8; nt++)
                    mma_tf32(acc[mt][nt], a[mt], b[nt]);
        }
    }

    // ---- epilogue 2: node_emb = acc + b2 ----
    float bsv2[8][2];
#pragma unroll
    for (int nt = 0; nt < 8; nt++)
#pragma unroll
        for (int q = 0; q < 2; q++)
            bsv2[nt][q] = b2[wcol + nt * 8 + lc * 2 + q];
#pragma unroll
    for (int mt = 0; mt < 2; mt++)
#pragma unroll
        for (int half = 0; half < 2; half++) {
            int row = wrow + mt * 16 + lr + half * 8;
            int n = n0 + row;
            if (n >= NN) continue;
#pragma unroll
            for (int nt = 0; nt < 8; nt++)
#pragma unroll
                for (int q = 0; q < 2; q++) {
                    int col = wcol + nt * 8 + lc * 2 + q;
                    out[(size_t)n * 128 + col] =
                        acc[mt][nt][half * 2 + q] + bsv2[nt][q];
                }
        }
}

// ---------------- pool ---------------------------------------------------------
__global__ void k_pool(const int* __restrict__ batch, const float* __restrict__ emb) {
    int c = blockIdx.x;
    int j = threadIdx.x;
    int n0 = c * 32;
    __shared__ int sb[32];
    if (j < 32) sb[j] = (n0 + j < NN) ? batch[n0 + j] : -1;
    __syncthreads();
    float acc = 0.f;
    int bcur = sb[0];
    for (int m = 0; m < 32; m++) {
        int b = sb[m];
        if (b < 0) break;
        if (b != bcur) {
            atomicAdd(&g_gsum[bcur * HH + j], acc);
            acc = 0.f;
            bcur = b;
        }
        acc += emb[(size_t)(n0 + m) * HH + j];
    }
    if (bcur >= 0) atomicAdd(&g_gsum[bcur * HH + j], acc);
    if (j == 0) {
        float cn = 0.f;
        int bc = sb[0];
        for (int m = 0; m < 32; m++) {
            int b = sb[m];
            if (b < 0) break;
            if (b != bc) { atomicAdd(&g_cnt[bc], cn); cn = 0.f; bc = b; }
            cn += 1.f;
        }
        if (bc >= 0) atomicAdd(&g_cnt[bc], cn);
    }
}

__global__ void k_finish(float* __restrict__ out_graph) {
    int i = blockIdx.x * blockDim.x + threadIdx.x;
    if (i >= BB * HH) return;
    out_graph[i] = g_gsum[i] / fmaxf(g_cnt[i >> 7], 1.f);
}

// ---------------- launcher ------------------------------------------------------
extern "C" void kernel_launch(void* const* d_in, const int* in_sizes, int n_in,
                              void* d_out, int out_size) {
    const float* x      = (const float*)d_in[0];
    const int*   ei     = (const int*)  d_in[1];
    const float* ea     = (const float*)d_in[2];
    const int*   batch  = (const int*)  d_in[3];
    const float* in_W   = (const float*)d_in[4];
    const float* in_b   = (const float*)d_in[5];
    const float* edge_W = (const float*)d_in[6];
    const float* edge_b = (const float*)d_in[7];
    const float* mlp_W1 = (const float*)d_in[8];
    const float* mlp_b1 = (const float*)d_in[9];
    const float* bn1_g  = (const float*)d_in[10];
    const float* bn1_b  = (const float*)d_in[11];
    const float* bn1_rm = (const float*)d_in[12];
    const float* bn1_rv = (const float*)d_in[13];
    const float* mlp_W2 = (const float*)d_in[14];
    const float* mlp_b2 = (const float*)d_in[15];
    const float* bn2_g  = (const float*)d_in[16];
    const float* bn2_b  = (const float*)d_in[17];
    const float* bn2_rm = (const float*)d_in[18];
    const float* bn2_rv = (const float*)d_in[19];
    const float* eps    = (const float*)d_in[20];
    const float* ln_g   = (const float*)d_in[21];
    const float* ln_b   = (const float*)d_in[22];
    const float* out_W1 = (const float*)d_in[23];
    const float* out_b1 = (const float*)d_in[24];
    const float* out_W2 = (const float*)d_in[25];
    const float* out_b2 = (const float*)d_in[26];

    float* node_emb  = (float*)d_out;
    float* graph_emb = (float*)d_out + (size_t)NN * HH;

    float* g_hcat_p; cudaGetSymbolAddress((void**)&g_hcat_p, g_hcat);
    float* g_agg_p;  cudaGetSymbolAddress((void**)&g_agg_p,  g_agg);
    float* g_z1_p;   cudaGetSymbolAddress((void**)&g_z1_p,   g_z1);
    float* g_wtf_p;  cudaGetSymbolAddress((void**)&g_wtf_p,  g_wtf);

    const int SM256 = 3 * (64 * 80 + 2 * 4 * 32 * 80);   // 76800
    const int SM128 = 3 * (128 * 80 + 2 * 2 * 32 * 80);  // 61440
    const int SMOUT = 67584 + 3 * 10240;                 // 98304
    cudaFuncSetAttribute(k_gemm<128, 256, 0>,
                         cudaFuncAttributeMaxDynamicSharedMemorySize, SM256);
    cudaFuncSetAttribute(k_gemm<256, 128, 1>,
                         cudaFuncAttributeMaxDynamicSharedMemorySize, SM128);
    cudaFuncSetAttribute(k_gemm_out,
                         cudaFuncAttributeMaxDynamicSharedMemorySize, SMOUT);

    const int NT = 256;
    k_prep<<<(WTOT + NT - 1) / NT, NT>>>(mlp_W1, mlp_W2, out_W1, out_W2);
    k_input<<<(NN * HH + NT - 1) / NT, NT>>>(x, in_W, in_b);

    // CSR build
    k_count<<<(EE + NT - 1) / NT, NT>>>(ei);
    k_scan1<<<(NN + 1023) / 1024, 256>>>();
    k_scan2<<<1, 128>>>((NN + 1023) / 1024);
    k_place<<<(EE + NT - 1) / NT, NT>>>(ei, ea);

    const int grid128 = (NN + 127) / 128;
    const int grid64  = (NN + 63) / 64;
    for (int l = 0; l < LL; l++) {
        k_gather<<<(NN * 32 + NT - 1) / NT, NT>>>(edge_W, edge_b, eps, l);
        k_gemm<128, 256, 0><<<grid64, 256, SM256>>>(
            g_agg_p, g_wtf_p + W1OFF + (size_t)l * 128 * 256, mlp_b1 + l * 256,
            bn1_g + l * 256, bn1_b + l * 256, bn1_rm + l * 256, bn1_rv + l * 256,
            nullptr, nullptr, nullptr, g_z1_p);
        k_gemm<256, 128, 1><<<grid128, 256, SM128>>>(
            g_z1_p, g_wtf_p + W2OFF + (size_t)l * 256 * 128, mlp_b2 + l * 128,
            bn2_g + l * 128, bn2_b + l * 128, bn2_rm + l * 128, bn2_rv + l * 128,
            g_hcat_p + l * HH, ln_g + l * 128, ln_b + l * 128,
            g_hcat_p + (l + 1) * HH);
    }
    // fused output head: node_emb = relu(cat @ out_W1 + b1) @ out_W2 + b2
    k_gemm_out<<<grid128, 256, SMOUT>>>(
        g_hcat_p, g_wtf_p + O1OFF, g_wtf_p + O2OFF, out_b1, out_b2, node_emb);

    k_pool<<<(NN + 31) / 32, 128>>>(batch, node_emb);
    k_finish<<<(BB * HH + NT - 1) / NT, NT>>>(graph_emb);
}

// round 8
// speedup vs baseline: 1.1795x; 1.1074x over previous
#include <cuda_runtime.h>
#include <math.h>
#include <stdint.h>

#define NN 100000
#define EE 600000
#define HH 128
#define LL 3
#define BB 16
#define NF 12
#define EF 3
#define BN_EPS 1e-5f
#define LN_EPS 1e-5f

// permuted tf32 weight scratch offsets (floats)
#define W1OFF 0                         // 3 x (128*256)
#define W2OFF (LL * 128 * 256)          // 3 x (256*128)
#define O1OFF (W2OFF + LL * 256 * 128)  // 512*128
#define O2OFF (O1OFF + 512 * 128)       // 128*128
#define WTOT  (O2OFF + 128 * 128)

// ---------------- scratch (static device globals; no runtime alloc) ----------
__device__ __align__(128) float g_hcat[(size_t)NN * 4 * HH];
__device__ __align__(128) float g_agg [(size_t)NN * HH];
__device__ __align__(128) float g_wtf [WTOT];
__device__ float g_gsum[BB * HH];
__device__ float g_cnt [BB];
__device__ int   g_deg [NN];
__device__ int   g_rows[NN];
__device__ int   g_fill[NN];
__device__ __align__(128) float4 g_epack[EE];
__device__ int   g_bsum[128];
__device__ int   g_boff[128];

// ---------------- helpers ----------------------------------------------------
__device__ __forceinline__ uint32_t f2tf(float f) {
    uint32_t r;
    asm("cvt.rna.tf32.f32 %0, %1;" : "=r"(r) : "f"(f));
    return r;
}
__device__ __forceinline__ void mma_tf32(float* c, const uint32_t* a, const uint32_t* b) {
    asm volatile(
        "mma.sync.aligned.m16n8k8.row.col.f32.tf32.tf32.f32 "
        "{%0,%1,%2,%3},{%4,%5,%6,%7},{%8,%9},{%0,%1,%2,%3};\n"
        : "+f"(c[0]), "+f"(c[1]), "+f"(c[2]), "+f"(c[3])
        : "r"(a[0]), "r"(a[1]), "r"(a[2]), "r"(a[3]), "r"(b[0]), "r"(b[1]));
}
__device__ __forceinline__ uint32_t sptr(const void* p) {
    return (uint32_t)__cvta_generic_to_shared(p);
}
__device__ __forceinline__ void cp16(uint32_t d, const void* s, int sz) {
    asm volatile("cp.async.cg.shared.global [%0], [%1], 16, %2;\n"
                 :: "r"(d), "l"(s), "r"(sz));
}
__device__ __forceinline__ void cp_commit() {
    asm volatile("cp.async.commit_group;\n" ::: "memory");
}
template <int N> __device__ __forceinline__ void cp_wait() {
    asm volatile("cp.async.wait_group %0;\n" :: "n"(N) : "memory");
}

// ---------------- prep: zero counters + permute/convert ALL weights ------------
// fragment-major: i = (((s*NWG + nw)*32 + lane)*4 + g)*4 + e
//   k = 8s + (lane&3) + 4*(e&1), n = nw*64 + (2g + (e>>1))*8 + (lane>>2)
__global__ void k_prep(const float* __restrict__ w1, const float* __restrict__ w2,
                       const float* __restrict__ o1, const float* __restrict__ o2) {
    int i = blockIdx.x * blockDim.x + threadIdx.x;
    if (i < BB * HH) g_gsum[i] = 0.f;
    if (i < BB) g_cnt[i] = 0.f;
    if (i < NN) { g_deg[i] = 0; g_fill[i] = 0; }
    if (i >= WTOT) return;
    const float* src;
    int K, N, rel;
    if (i < W2OFF) {
        int l = i >> 15; rel = i & 32767;
        src = w1 + (size_t)l * 32768; K = 128; N = 256;
    } else if (i < O1OFF) {
        int j = i - W2OFF;
        int l = j >> 15; rel = j & 32767;
        src = w2 + (size_t)l * 32768; K = 256; N = 128;
    } else if (i < O2OFF) {
        rel = i - O1OFF; src = o1; K = 512; N = 128;
    } else {
        rel = i - O2OFF; src = o2; K = 128; N = 128;
    }
    int e = rel & 3, g = (rel >> 2) & 3, lane = (rel >> 4) & 31;
    int r = rel >> 9;
    int NWG = N >> 6;
    int nw = r % NWG, s = r / NWG;
    int lc = lane & 3, lr = lane >> 2;
    int k = 8 * s + lc + 4 * (e & 1);
    int n = nw * 64 + (2 * g + (e >> 1)) * 8 + lr;
    g_wtf[i] = __uint_as_float(f2tf(src[(size_t)k * N + n]));
}

__global__ void k_input(const float* __restrict__ x, const float* __restrict__ W,
                        const float* __restrict__ b) {
    int idx = blockIdx.x * blockDim.x + threadIdx.x;
    if (idx >= NN * HH) return;
    int n = idx >> 7, j = idx & 127;
    const float* xr = x + (size_t)n * NF;
    float acc = b[j];
#pragma unroll
    for (int f = 0; f < NF; f++) acc += xr[f] * W[f * HH + j];
    g_hcat[(size_t)n * 512 + j] = acc;
}

// ---------------- CSR build ----------------------------------------------------
__global__ void k_count(const int* __restrict__ ei) {
    int e = blockIdx.x * blockDim.x + threadIdx.x;
    if (e < EE) atomicAdd(&g_deg[ei[EE + e]], 1);
}
__global__ void k_scan1() {
    __shared__ int ss[256];
    int t = threadIdx.x;
    int base = blockIdx.x * 1024;
    int v[4], s = 0;
#pragma unroll
    for (int j = 0; j < 4; j++) {
        int i = base + t * 4 + j;
        v[j] = (i < NN) ? g_deg[i] : 0;
        s += v[j];
    }
    ss[t] = s;
    __syncthreads();
#pragma unroll
    for (int off = 1; off < 256; off <<= 1) {
        int a = (t >= off) ? ss[t - off] : 0;
        __syncthreads();
        ss[t] += a;
        __syncthreads();
    }
    if (t == 255) g_bsum[blockIdx.x] = ss[255];
    int run = ss[t] - s;
#pragma unroll
    for (int j = 0; j < 4; j++) {
        int i = base + t * 4 + j;
        if (i < NN) g_rows[i] = run;
        run += v[j];
    }
}
__global__ void k_scan2(int nb) {
    __shared__ int ss[128];
    int t = threadIdx.x;
    int v = (t < nb) ? g_bsum[t] : 0;
    ss[t] = v;
    __syncthreads();
#pragma unroll
    for (int off = 1; off < 128; off <<= 1) {
        int a = (t >= off) ? ss[t - off] : 0;
        __syncthreads();
        ss[t] += a;
        __syncthreads();
    }
    if (t < nb) g_boff[t] = ss[t] - v;
}
__global__ void k_place(const int* __restrict__ ei, const float* __restrict__ ea) {
    int e = blockIdx.x * blockDim.x + threadIdx.x;
    if (e >= EE) return;
    int d = ei[EE + e];
    int p = g_rows[d] + g_boff[d >> 10] + atomicAdd(&g_fill[d], 1);
    float4 r;
    r.x = __int_as_float(ei[e]);
    r.y = ea[e * 3 + 0];
    r.z = ea[e * 3 + 1];
    r.w = ea[e * 3 + 2];
    g_epack[p] = r;
}

// ---------------- per-node gather aggregation (no atomics, 4-way MLP) ---------
__global__ void k_gather(const float* __restrict__ eW, const float* __restrict__ eb,
                         const float* __restrict__ eps, int layer) {
    int warp = (blockIdx.x * blockDim.x + threadIdx.x) >> 5;
    int lane = threadIdx.x & 31;
    if (warp >= NN) return;
    int j = lane * 4;
    const float* W = eW + layer * EF * HH;
    float4 w0 = *(const float4*)(W + 0 * HH + j);
    float4 w1 = *(const float4*)(W + 1 * HH + j);
    float4 w2 = *(const float4*)(W + 2 * HH + j);
    float4 bv = *(const float4*)(eb + layer * HH + j);
    const float* hl = g_hcat + (size_t)layer * HH;
    float4 hd = *(const float4*)(hl + (size_t)warp * 512 + j);
    int start = g_rows[warp] + g_boff[warp >> 10];
    int deg = g_deg[warp];
    const float4* ep = g_epack + start;

    float e1 = 1.f + eps[layer];
    float dg = (float)deg;
    float ax = e1 * hd.x + dg * bv.x;
    float ay = e1 * hd.y + dg * bv.y;
    float az = e1 * hd.z + dg * bv.z;
    float aw = e1 * hd.w + dg * bv.w;
    float bx = 0.f, by = 0.f, bz = 0.f, bw = 0.f;

    int k = 0;
    for (; k + 4 <= deg; k += 4) {
        float4 r0 = ep[k], r1 = ep[k + 1], r2 = ep[k + 2], r3 = ep[k + 3];
        float4 h0 = *(const float4*)(hl + (size_t)__float_as_int(r0.x) * 512 + j);
        float4 h1 = *(const float4*)(hl + (size_t)__float_as_int(r1.x) * 512 + j);
        float4 h2 = *(const float4*)(hl + (size_t)__float_as_int(r2.x) * 512 + j);
        float4 h3 = *(const float4*)(hl + (size_t)__float_as_int(r3.x) * 512 + j);
        ax += h0.x + r0.y * w0.x + r0.z * w1.x + r0.w * w2.x;
        ay += h0.y + r0.y * w0.y + r0.z * w1.y + r0.w * w2.y;
        az += h0.z + r0.y * w0.z + r0.z * w1.z + r0.w * w2.z;
        aw += h0.w + r0.y * w0.w + r0.z * w1.w + r0.w * w2.w;
        bx += h1.x + r1.y * w0.x + r1.z * w1.x + r1.w * w2.x;
        by += h1.y + r1.y * w0.y + r1.z * w1.y + r1.w * w2.y;
        bz += h1.z + r1.y * w0.z + r1.z * w1.z + r1.w * w2.z;
        bw += h1.w + r1.y * w0.w + r1.z * w1.w + r1.w * w2.w;
        ax += h2.x + r2.y * w0.x + r2.z * w1.x + r2.w * w2.x;
        ay += h2.y + r2.y * w0.y + r2.z * w1.y + r2.w * w2.y;
        az += h2.z + r2.y * w0.z + r2.z * w1.z + r2.w * w2.z;
        aw += h2.w + r2.y * w0.w + r2.z * w1.w + r2.w * w2.w;
        bx += h3.x + r3.y * w0.x + r3.z * w1.x + r3.w * w2.x;
        by += h3.y + r3.y * w0.y + r3.z * w1.y + r3.w * w2.y;
        bz += h3.z + r3.y * w0.z + r3.z * w1.z + r3.w * w2.z;
        bw += h3.w + r3.y * w0.w + r3.z * w1.w + r3.w * w2.w;
    }
    for (; k < deg; k++) {
        float4 r0 = ep[k];
        float4 h0 = *(const float4*)(hl + (size_t)__float_as_int(r0.x) * 512 + j);
        ax += h0.x + r0.y * w0.x + r0.z * w1.x + r0.w * w2.x;
        ay += h0.y + r0.y * w0.y + r0.z * w1.y + r0.w * w2.y;
        az += h0.z + r0.y * w0.z + r0.z * w1.z + r0.w * w2.z;
        aw += h0.w + r0.y * w0.w + r0.z * w1.w + r0.w * w2.w;
    }
    float4 o;
    o.x = __uint_as_float(f2tf(ax + bx));
    o.y = __uint_as_float(f2tf(ay + by));
    o.z = __uint_as_float(f2tf(az + bz));
    o.w = __uint_as_float(f2tf(aw + bw));
    *(float4*)(g_agg + (size_t)warp * HH + j) = o;
}

// ---------------- fused GIN MLP: agg -> mlp1(bn,relu) -> mlp2(bn,relu)+res+LN --
// BM=64. Phase 1: agg[64,128] @ W1p -> z[64,256] (smem, tf32 bits, stride 260).
// Phase 2: z @ W2p (K=256, W2 ring) -> bn2+relu+residual -> LN -> hcat (OS=512).
__global__ void __launch_bounds__(256, 2)
k_mlp(const float* __restrict__ A, const float* __restrict__ W1p,
      const float* __restrict__ W2p,
      const float* __restrict__ b1v, const float* __restrict__ g1,
      const float* __restrict__ bt1, const float* __restrict__ rm1,
      const float* __restrict__ rv1,
      const float* __restrict__ b2v, const float* __restrict__ g2,
      const float* __restrict__ bt2, const float* __restrict__ rm2,
      const float* __restrict__ rv2,
      const float* __restrict__ hres,
      const float* __restrict__ lng, const float* __restrict__ lnb,
      float* __restrict__ out) {
    constexpr int BM = 64, KC = 16;
    constexpr int NWG1 = 4, NC1 = 256, CH1 = 8;    // phase 1 (K=128)
    constexpr int NWG2 = 2, NC2 = 128, CH2 = 16;   // phase 2 (K=256)
    constexpr int ABYTES = BM * 80;                // 5120
    constexpr int B1BYTES = 2 * NWG1 * 32 * 80;    // 20480
    constexpr int STG1 = ABYTES + B1BYTES;         // 25600 (x3 = 76800)
    constexpr int B2BYTES = 2 * NWG2 * 32 * 80;    // 10240
    constexpr int ZBYTES = BM * 260 * 4;           // 66560
    constexpr int W2RING = ZBYTES;                 // [66560, 97280)

    extern __shared__ char dsm[];
    __shared__ float red[BM * 4];
    uint32_t sb = sptr(dsm);

    int t = threadIdx.x;
    int lane = t & 31, wid = t >> 5;
    int lr = lane >> 2, lc = lane & 3;
    int n0 = blockIdx.x * BM;

    // ---- phase 1 warp layout: 2 M x 4 N, warp tile 32x64 ----
    int mw = wid >> 2, nw = wid & 3;
    int wrow = mw * 32, wcol = nw * 64;

    float acc[2][8][4];
#pragma unroll
    for (int mt = 0; mt < 2; mt++)
#pragma unroll
        for (int nt = 0; nt < 8; nt++)
#pragma unroll
            for (int i = 0; i < 4; i++) acc[mt][nt][i] = 0.f;

    auto load_t1 = [&](int c, int st) {
        uint32_t ab = sb + st * STG1;
        uint32_t bb = ab + ABYTES;
        {   // A: 64 rows x 16 floats = 256 float4
            int r = t >> 2, c4 = t & 3;
            int n = n0 + r;
            const float* src = A + (size_t)(n < NN ? n : 0) * 128 + c * KC + c4 * 4;
            cp16(ab + r * 80 + c4 * 16, src, n < NN ? 16 : 0);
        }
#pragma unroll
        for (int i = 0; i < 4; i++) {   // B1: 1024 float4
            int f = t + i * 256;
            cp16(bb + (f >> 2) * 80 + (f & 3) * 16,
                 W1p + (size_t)c * KC * NC1 + f * 4, 16);
        }
    };
    auto load_w2 = [&](int c2, int jb) {
        uint32_t bb = sb + W2RING + jb * B2BYTES;
#pragma unroll
        for (int i = 0; i < 2; i++) {   // B2: 512 float4
            int f = t + i * 256;
            cp16(bb + (f >> 2) * 80 + (f & 3) * 16,
                 W2p + (size_t)c2 * KC * NC2 + f * 4, 16);
        }
    };

    load_t1(0, 0);
    cp_commit();
    load_t1(1, 1);
    cp_commit();
    for (int c = 0; c < CH1; c++) {
        int st = c % 3;
        if (c + 1 < CH1) cp_wait<1>(); else cp_wait<0>();
        __syncthreads();
        if (c + 2 < CH1) {
            load_t1(c + 2, (c + 2) % 3);
            cp_commit();
        }
        const float* As = (const float*)(dsm + st * STG1);
        const char*  Bb = dsm + st * STG1 + ABYTES;
#pragma unroll
        for (int ks = 0; ks < 2; ks++) {
            int kk = ks * 8;
            uint32_t a[2][4];
#pragma unroll
            for (int mt = 0; mt < 2; mt++) {
                int base = (wrow + mt * 16 + lr) * 20 + kk + lc;
                a[mt][0] = __float_as_uint(As[base]);
                a[mt][1] = __float_as_uint(As[base + 160]);
                a[mt][2] = __float_as_uint(As[base + 4]);
                a[mt][3] = __float_as_uint(As[base + 164]);
            }
            const float4* bf =
                (const float4*)(Bb + ((size_t)((ks * NWG1 + nw) * 32 + lane)) * 80);
            uint32_t b[8][2];
#pragma unroll
            for (int g = 0; g < 4; g++) {
                float4 f4 = bf[g];
                b[2 * g + 0][0] = __float_as_uint(f4.x);
                b[2 * g + 0][1] = __float_as_uint(f4.y);
                b[2 * g + 1][0] = __float_as_uint(f4.z);
                b[2 * g + 1][1] = __float_as_uint(f4.w);
            }
#pragma unroll
            for (int mt = 0; mt < 2; mt++)
#pragma unroll
                for (int nt = 0; nt < 8; nt++)
                    mma_tf32(acc[mt][nt], a[mt], b[nt]);
        }
    }
    __syncthreads();   // ring fully consumed before reuse

    // prefetch first two W2 chunks (region above the z stash)
    load_w2(0, 0);
    cp_commit();
    load_w2(1, 1);
    cp_commit();

    // ---- z = tf32(relu(bn1(acc + b1))) -> smem stash ----
    float* Zs = (float*)dsm;
    {
        float bsv[8][2], sc[8][2], sh[8][2];
#pragma unroll
        for (int nt = 0; nt < 8; nt++)
#pragma unroll
            for (int q = 0; q < 2; q++) {
                int col = wcol + nt * 8 + lc * 2 + q;
                bsv[nt][q] = b1v[col];
                float s = g1[col] * rsqrtf(rv1[col] + BN_EPS);
                sc[nt][q] = s;
                sh[nt][q] = bt1[col] - rm1[col] * s;
            }
#pragma unroll
        for (int mt = 0; mt < 2; mt++)
#pragma unroll
            for (int half = 0; half < 2; half++) {
                int row = wrow + mt * 16 + lr + half * 8;
#pragma unroll
                for (int nt = 0; nt < 8; nt++)
#pragma unroll
                    for (int q = 0; q < 2; q++) {
                        int col = wcol + nt * 8 + lc * 2 + q;
                        float v = acc[mt][nt][half * 2 + q] + bsv[nt][q];
                        v = fmaxf(v * sc[nt][q] + sh[nt][q], 0.f);
                        Zs[row * 260 + col] = __uint_as_float(f2tf(v));
                    }
            }
    }
    __syncthreads();

    // ---- phase 2: z @ W2, warp tile 16x64, layout 4 M x 2 N ----
    int mw2 = wid >> 1, nw2 = wid & 1;
    int wrow2 = mw2 * 16, wcol2 = nw2 * 64;
    float acc2[8][4];
#pragma unroll
    for (int nt = 0; nt < 8; nt++)
#pragma unroll
        for (int i = 0; i < 4; i++) acc2[nt][i] = 0.f;

    for (int c2 = 0; c2 < CH2; c2++) {
        int jb = c2 % 3;
        if (c2 + 1 < CH2) cp_wait<1>(); else cp_wait<0>();
        __syncthreads();
        if (c2 + 2 < CH2) {
            load_w2(c2 + 2, (c2 + 2) % 3);
            cp_commit();
        }
        const char* Bb = dsm + W2RING + jb * B2BYTES;
#pragma unroll
        for (int ks = 0; ks < 2; ks++) {
            int kk = ks * 8;
            uint32_t a[4];
            {
                int base = (wrow2 + lr) * 260 + c2 * KC + kk + lc;
                a[0] = __float_as_uint(Zs[base]);
                a[1] = __float_as_uint(Zs[base + 8 * 260]);
                a[2] = __float_as_uint(Zs[base + 4]);
                a[3] = __float_as_uint(Zs[base + 8 * 260 + 4]);
            }
            const float4* bf =
                (const float4*)(Bb + ((size_t)((ks * NWG2 + nw2) * 32 + lane)) * 80);
            uint32_t b[8][2];
#pragma unroll
            for (int g = 0; g < 4; g++) {
                float4 f4 = bf[g];
                b[2 * g + 0][0] = __float_as_uint(f4.x);
                b[2 * g + 0][1] = __float_as_uint(f4.y);
                b[2 * g + 1][0] = __float_as_uint(f4.z);
                b[2 * g + 1][1] = __float_as_uint(f4.w);
            }
#pragma unroll
            for (int nt = 0; nt < 8; nt++)
                mma_tf32(acc2[nt], a, b[nt]);
        }
    }

    // ---- epilogue: bn2+relu + residual, LN, write hcat slot (stride 512) ----
    float bsv2[8][2], sc2[8][2], sh2[8][2];
#pragma unroll
    for (int nt = 0; nt < 8; nt++)
#pragma unroll
        for (int q = 0; q < 2; q++) {
            int col = wcol2 + nt * 8 + lc * 2 + q;
            bsv2[nt][q] = b2v[col];
            float s = g2[col] * rsqrtf(rv2[col] + BN_EPS);
            sc2[nt][q] = s;
            sh2[nt][q] = bt2[col] - rm2[col] * s;
        }
#pragma unroll
    for (int half = 0; half < 2; half++) {
        int row = wrow2 + lr + half * 8;
        int n = n0 + row;
        float s = 0.f, sq = 0.f;
#pragma unroll
        for (int nt = 0; nt < 8; nt++)
#pragma unroll
            for (int q = 0; q < 2; q++) {
                int col = wcol2 + nt * 8 + lc * 2 + q;
                float v = acc2[nt][half * 2 + q] + bsv2[nt][q];
                v = fmaxf(v * sc2[nt][q] + sh2[nt][q], 0.f);
                if (n < NN) v += hres[(size_t)n * 512 + col];
                acc2[nt][half * 2 + q] = v;
                s += v;
                sq += v * v;
            }
        s  += __shfl_xor_sync(0xffffffffu, s, 1);
        sq += __shfl_xor_sync(0xffffffffu, sq, 1);
        s  += __shfl_xor_sync(0xffffffffu, s, 2);
        sq += __shfl_xor_sync(0xffffffffu, sq, 2);
        if (lc == 0) {
            red[(row * 2 + nw2) * 2 + 0] = s;
            red[(row * 2 + nw2) * 2 + 1] = sq;
        }
    }
    __syncthreads();
#pragma unroll
    for (int half = 0; half < 2; half++) {
        int row = wrow2 + lr + half * 8;
        int n = n0 + row;
        if (n >= NN) continue;
        float s  = red[(row * 2 + 0) * 2 + 0] + red[(row * 2 + 1) * 2 + 0];
        float sq = red[(row * 2 + 0) * 2 + 1] + red[(row * 2 + 1) * 2 + 1];
        float mu = s * (1.f / 128.f);
        float var = sq * (1.f / 128.f) - mu * mu;
        float inv = rsqrtf(var + LN_EPS);
#pragma unroll
        for (int nt = 0; nt < 8; nt++)
#pragma unroll
            for (int q = 0; q < 2; q++) {
                int col = wcol2 + nt * 8 + lc * 2 + q;
                float v = acc2[nt][half * 2 + q];
                out[(size_t)n * 512 + col] = (v - mu) * inv * lng[col] + lnb[col];
            }
    }
}

// ---------------- fused output head: node_emb = relu(cat@W1+b1)@W2 + b2 -------
__global__ void __launch_bounds__(256, 2)
k_gemm_out(const float* __restrict__ A, const float* __restrict__ W1p,
           const float* __restrict__ W2p,
           const float* __restrict__ b1, const float* __restrict__ b2,
           float* __restrict__ out) {
    constexpr int NWG = 2, BM = 128, KC = 16, K = 512, NC = 128;
    constexpr int CH = K / KC;
    constexpr int ABYTES = BM * 80;
    constexpr int BBYTES = 2 * NWG * 32 * 80;
    constexpr int STG = ABYTES + BBYTES;
    constexpr int B2OFF = 67584;

    extern __shared__ char dsm[];
    uint32_t sb = sptr(dsm);

    int t = threadIdx.x;
    int lane = t & 31, wid = t >> 5;
    int mw = wid >> 1, nw = wid & 1;
    int wrow = mw * 32, wcol = nw * 64;
    int lr = lane >> 2, lc = lane & 3;
    int n0 = blockIdx.x * BM;

    float acc[2][8][4];
#pragma unroll
    for (int mt = 0; mt < 2; mt++)
#pragma unroll
        for (int nt = 0; nt < 8; nt++)
#pragma unroll
            for (int i = 0; i < 4; i++) acc[mt][nt][i] = 0.f;

    auto load_tiles = [&](int c, int st) {
        uint32_t ab = sb + st * STG;
        uint32_t bb = ab + ABYTES;
#pragma unroll
        for (int i = 0; i < 2; i++) {
            int f = t + i * 256;
            int r = f >> 2, c4 = f & 3;
            int n = n0 + r;
            const float* src = A + (size_t)(n < NN ? n : 0) * K + c * KC + c4 * 4;
            cp16(ab + r * 80 + c4 * 16, src, n < NN ? 16 : 0);
        }
#pragma unroll
        for (int i = 0; i < 2; i++) {
            int f = t + i * 256;
            cp16(bb + (f >> 2) * 80 + (f & 3) * 16,
                 W1p + (size_t)c * KC * NC + f * 4, 16);
        }
    };
    auto load_w2 = [&](int c2, int jbuf) {
        uint32_t bb = sb + B2OFF + jbuf * BBYTES;
#pragma unroll
        for (int i = 0; i < 2; i++) {
            int f = t + i * 256;
            cp16(bb + (f >> 2) * 80 + (f & 3) * 16,
                 W2p + (size_t)c2 * KC * NC + f * 4, 16);
        }
    };

    load_tiles(0, 0);
    cp_commit();
    load_tiles(1, 1);
    cp_commit();
    for (int c = 0; c < CH; c++) {
        int st = c % 3;
        if (c + 1 < CH) cp_wait<1>(); else cp_wait<0>();
        __syncthreads();
        if (c + 2 < CH) {
            load_tiles(c + 2, (c + 2) % 3);
            cp_commit();
        }
        const float* As = (const float*)(dsm + st * STG);
        const char*  Bb = dsm + st * STG + ABYTES;
#pragma unroll
        for (int ks = 0; ks < 2; ks++) {
            int kk = ks * 8;
            uint32_t a[2][4];
#pragma unroll
            for (int mt = 0; mt < 2; mt++) {
                int base = (wrow + mt * 16 + lr) * 20 + kk + lc;
                a[mt][0] = f2tf(As[base]);
                a[mt][1] = f2tf(As[base + 160]);
                a[mt][2] = f2tf(As[base + 4]);
                a[mt][3] = f2tf(As[base + 164]);
            }
            const float4* bf =
                (const float4*)(Bb + ((size_t)((ks * NWG + nw) * 32 + lane)) * 80);
            uint32_t b[8][2];
#pragma unroll
            for (int g = 0; g < 4; g++) {
                float4 f4 = bf[g];
                b[2 * g + 0][0] = __float_as_uint(f4.x);
                b[2 * g + 0][1] = __float_as_uint(f4.y);
                b[2 * g + 1][0] = __float_as_uint(f4.z);
                b[2 * g + 1][1] = __float_as_uint(f4.w);
            }
#pragma unroll
            for (int mt = 0; mt < 2; mt++)
#pragma unroll
                for (int nt = 0; nt < 8; nt++)
                    mma_tf32(acc[mt][nt], a[mt], b[nt]);
        }
    }
    __syncthreads();

    load_w2(0, 0);
    cp_commit();
    load_w2(1, 1);
    cp_commit();

    float* Zs = (float*)dsm;
    {
        float bsv[8][2];
#pragma unroll
        for (int nt = 0; nt < 8; nt++)
#pragma unroll
            for (int q = 0; q < 2; q++)
                bsv[nt][q] = b1[wcol + nt * 8 + lc * 2 + q];
#pragma unroll
        for (int mt = 0; mt < 2; mt++)
#pragma unroll
            for (int half = 0; half < 2; half++) {
                int row = wrow + mt * 16 + lr + half * 8;
#pragma unroll
                for (int nt = 0; nt < 8; nt++)
#pragma unroll
                    for (int q = 0; q < 2; q++) {
                        int col = wcol + nt * 8 + lc * 2 + q;
                        float v = fmaxf(acc[mt][nt][half * 2 + q] + bsv[nt][q], 0.f);
                        Zs[row * 132 + col] = __uint_as_float(f2tf(v));
                    }
            }
    }
    __syncthreads();

#pragma unroll
    for (int mt = 0; mt < 2; mt++)
#pragma unroll
        for (int nt = 0; nt < 8; nt++)
#pragma unroll
            for (int i = 0; i < 4; i++) acc[mt][nt][i] = 0.f;

    for (int c2 = 0; c2 < 8; c2++) {
        int jb = c2 % 3;
        if (c2 + 1 < 8) cp_wait<1>(); else cp_wait<0>();
        __syncthreads();
        if (c2 + 2 < 8) {
            load_w2(c2 + 2, (c2 + 2) % 3);
            cp_commit();
        }
        const char* Bb = dsm + B2OFF + jb * BBYTES;
#pragma unroll
        for (int ks = 0; ks < 2; ks++) {
            int kk = ks * 8;
            uint32_t a[2][4];
#pragma unroll
            for (int mt = 0; mt < 2; mt++) {
                int base = (wrow + mt * 16 + lr) * 132 + c2 * KC + kk + lc;
                a[mt][0] = __float_as_uint(Zs[base]);
                a[mt][1] = __float_as_uint(Zs[base + 8 * 132]);
                a[mt][2] = __float_as_uint(Zs[base + 4]);
                a[mt][3] = __float_as_uint(Zs[base + 8 * 132 + 4]);
            }
            const float4* bf =
                (const float4*)(Bb + ((size_t)((ks * NWG + nw) * 32 + lane)) * 80);
            uint32_t b[8][2];
#pragma unroll
            for (int g = 0; g < 4; g++) {
                float4 f4 = bf[g];
                b[2 * g + 0][0] = __float_as_uint(f4.x);
                b[2 * g + 0][1] = __float_as_uint(f4.y);
                b[2 * g + 1][0] = __float_as_uint(f4.z);
                b[2 * g + 1][1] = __float_as_uint(f4.w);
            }
#pragma unroll
            for (int mt = 0; mt < 2; mt++)
#pragma unroll
                for (int nt = 0; nt < 8; nt++)
                    mma_tf32(acc[mt][nt], a[mt], b[nt]);
        }
    }

    float bsv2[8][2];
#pragma unroll
    for (int nt = 0; nt < 8; nt++)
#pragma unroll
        for (int q = 0; q < 2; q++)
            bsv2[nt][q] = b2[wcol + nt * 8 + lc * 2 + q];
#pragma unroll
    for (int mt = 0; mt < 2; mt++)
#pragma unroll
        for (int half = 0; half < 2; half++) {
            int row = wrow + mt * 16 + lr + half * 8;
            int n = n0 + row;
            if (n >= NN) continue;
#pragma unroll
            for (int nt = 0; nt < 8; nt++)
#pragma unroll
                for (int q = 0; q < 2; q++) {
                    int col = wcol + nt * 8 + lc * 2 + q;
                    out[(size_t)n * 128 + col] =
                        acc[mt][nt][half * 2 + q] + bsv2[nt][q];
                }
        }
}

// ---------------- pool ---------------------------------------------------------
__global__ void k_pool(const int* __restrict__ batch, const float* __restrict__ emb) {
    int c = blockIdx.x;
    int j = threadIdx.x;
    int n0 = c * 32;
    __shared__ int sb[32];
    if (j < 32) sb[j] = (n0 + j < NN) ? batch[n0 + j] : -1;
    __syncthreads();
    float acc = 0.f;
    int bcur = sb[0];
    for (int m = 0; m < 32; m++) {
        int b = sb[m];
        if (b < 0) break;
        if (b != bcur) {
            atomicAdd(&g_gsum[bcur * HH + j], acc);
            acc = 0.f;
            bcur = b;
        }
        acc += emb[(size_t)(n0 + m) * HH + j];
    }
    if (bcur >= 0) atomicAdd(&g_gsum[bcur * HH + j], acc);
    if (j == 0) {
        float cn = 0.f;
        int bc = sb[0];
        for (int m = 0; m < 32; m++) {
            int b = sb[m];
            if (b < 0) break;
            if (b != bc) { atomicAdd(&g_cnt[bc], cn); cn = 0.f; bc = b; }
            cn += 1.f;
        }
        if (bc >= 0) atomicAdd(&g_cnt[bc], cn);
    }
}

__global__ void k_finish(float* __restrict__ out_graph) {
    int i = blockIdx.x * blockDim.x + threadIdx.x;
    if (i >= BB * HH) return;
    out_graph[i] = g_gsum[i] / fmaxf(g_cnt[i >> 7], 1.f);
}

// ---------------- launcher ------------------------------------------------------
extern "C" void kernel_launch(void* const* d_in, const int* in_sizes, int n_in,
                              void* d_out, int out_size) {
    const float* x      = (const float*)d_in[0];
    const int*   ei     = (const int*)  d_in[1];
    const float* ea     = (const float*)d_in[2];
    const int*   batch  = (const int*)  d_in[3];
    const float* in_W   = (const float*)d_in[4];
    const float* in_b   = (const float*)d_in[5];
    const float* edge_W = (const float*)d_in[6];
    const float* edge_b = (const float*)d_in[7];
    const float* mlp_W1 = (const float*)d_in[8];
    const float* mlp_b1 = (const float*)d_in[9];
    const float* bn1_g  = (const float*)d_in[10];
    const float* bn1_b  = (const float*)d_in[11];
    const float* bn1_rm = (const float*)d_in[12];
    const float* bn1_rv = (const float*)d_in[13];
    const float* mlp_W2 = (const float*)d_in[14];
    const float* mlp_b2 = (const float*)d_in[15];
    const float* bn2_g  = (const float*)d_in[16];
    const float* bn2_b  = (const float*)d_in[17];
    const float* bn2_rm = (const float*)d_in[18];
    const float* bn2_rv = (const float*)d_in[19];
    const float* eps    = (const float*)d_in[20];
    const float* ln_g   = (const float*)d_in[21];
    const float* ln_b   = (const float*)d_in[22];
    const float* out_W1 = (const float*)d_in[23];
    const float* out_b1 = (const float*)d_in[24];
    const float* out_W2 = (const float*)d_in[25];
    const float* out_b2 = (const float*)d_in[26];

    float* node_emb  = (float*)d_out;
    float* graph_emb = (float*)d_out + (size_t)NN * HH;

    float* g_hcat_p; cudaGetSymbolAddress((void**)&g_hcat_p, g_hcat);
    float* g_agg_p;  cudaGetSymbolAddress((void**)&g_agg_p,  g_agg);
    float* g_wtf_p;  cudaGetSymbolAddress((void**)&g_wtf_p,  g_wtf);

    const int SMMLP = 66560 + 3 * 10240;   // 97280 (covers 76800 phase-1 ring)
    const int SMOUT = 67584 + 3 * 10240;   // 98304
    cudaFuncSetAttribute(k_mlp,
                         cudaFuncAttributeMaxDynamicSharedMemorySize, SMMLP);
    cudaFuncSetAttribute(k_gemm_out,
                         cudaFuncAttributeMaxDynamicSharedMemorySize, SMOUT);

    const int NT = 256;
    k_prep<<<(WTOT + NT - 1) / NT, NT>>>(mlp_W1, mlp_W2, out_W1, out_W2);
    k_input<<<(NN * HH + NT - 1) / NT, NT>>>(x, in_W, in_b);

    // CSR build
    k_count<<<(EE + NT - 1) / NT, NT>>>(ei);
    k_scan1<<<(NN + 1023) / 1024, 256>>>();
    k_scan2<<<1, 128>>>((NN + 1023) / 1024);
    k_place<<<(EE + NT - 1) / NT, NT>>>(ei, ea);

    const int grid64  = (NN + 63) / 64;
    const int grid128 = (NN + 127) / 128;
    for (int l = 0; l < LL; l++) {
        k_gather<<<(NN * 32 + NT - 1) / NT, NT>>>(edge_W, edge_b, eps, l);
        k_mlp<<<grid64, 256, SMMLP>>>(
            g_agg_p,
            g_wtf_p + W1OFF + (size_t)l * 128 * 256,
            g_wtf_p + W2OFF + (size_t)l * 256 * 128,
            mlp_b1 + l * 256, bn1_g + l * 256, bn1_b + l * 256,
            bn1_rm + l * 256, bn1_rv + l * 256,
            mlp_b2 + l * 128, bn2_g + l * 128, bn2_b + l * 128,
            bn2_rm + l * 128, bn2_rv + l * 128,
            g_hcat_p + l * HH, ln_g + l * 128, ln_b + l * 128,
            g_hcat_p + (l + 1) * HH);
    }
    k_gemm_out<<<grid128, 256, SMOUT>>>(
        g_hcat_p, g_wtf_p + O1OFF, g_wtf_p + O2OFF, out_b1, out_b2, node_emb);

    k_pool<<<(NN + 31) / 32, 128>>>(batch, node_emb);
    k_finish<<<(BB * HH + NT - 1) / NT, NT>>>(graph_emb);
}